// round 1
// baseline (speedup 1.0000x reference)
#include <cuda_runtime.h>
#include <cuda_bf16.h>

#define N_NODES 50000
#define N_EDGES 800000
#define F_IN    512
#define F_HID   128
#define F_OUT   64
#define NBLK    196          // ceil(50000/256)

// ---------------- device scratch (static; no allocation allowed) -------------
__device__ int   g_indeg[N_NODES];
__device__ int   g_outdeg[N_NODES];
__device__ float g_outnorm[N_NODES];
__device__ float g_innorm[N_NODES];
__device__ int   g_scan[N_NODES];       // per-block inclusive scan of indeg
__device__ int   g_bsum[256];
__device__ int   g_bscan[256];
__device__ int   g_off[N_NODES + 1];    // CSR offsets (by dst)
__device__ int   g_cursor[N_NODES];
__device__ int   g_csr[N_EDGES];        // src node per CSR slot
__device__ float g_y1[(size_t)N_NODES * F_HID];  // (x*outnorm)@W1
__device__ float g_h [(size_t)N_NODES * F_HID];  // relu(agg*innorm + b1)
__device__ float g_y2[(size_t)N_NODES * F_OUT];  // (h*outnorm)@W2

// ---------------- degree / CSR construction --------------------------------
__global__ void k_zero_deg() {
    int i = blockIdx.x * blockDim.x + threadIdx.x;
    if (i < N_NODES) { g_indeg[i] = 0; g_outdeg[i] = 0; }
}

__global__ void k_degrees(const int* __restrict__ esrc, const int* __restrict__ edst) {
    int e = blockIdx.x * blockDim.x + threadIdx.x;
    if (e < N_EDGES) {
        atomicAdd(&g_outdeg[esrc[e]], 1);
        atomicAdd(&g_indeg [edst[e]], 1);
    }
}

// per-block inclusive scan of indeg + compute norms
__global__ void k_scan_block() {
    __shared__ int sh[256];
    int t = threadIdx.x;
    int i = blockIdx.x * 256 + t;
    int v = (i < N_NODES) ? g_indeg[i] : 0;
    sh[t] = v;
    __syncthreads();
    #pragma unroll
    for (int o = 1; o < 256; o <<= 1) {
        int x = (t >= o) ? sh[t - o] : 0;
        __syncthreads();
        sh[t] += x;
        __syncthreads();
    }
    if (i < N_NODES) {
        g_scan[i] = sh[t];
        g_outnorm[i] = rsqrtf(fmaxf((float)g_outdeg[i], 1.0f));
        g_innorm [i] = rsqrtf(fmaxf((float)g_indeg [i], 1.0f));
    }
    if (t == 255) g_bsum[blockIdx.x] = sh[255];
}

__global__ void k_scan_bsum() {
    __shared__ int sh[256];
    int t = threadIdx.x;
    sh[t] = (t < NBLK) ? g_bsum[t] : 0;
    __syncthreads();
    #pragma unroll
    for (int o = 1; o < 256; o <<= 1) {
        int x = (t >= o) ? sh[t - o] : 0;
        __syncthreads();
        sh[t] += x;
        __syncthreads();
    }
    if (t < NBLK) g_bscan[t] = sh[t];
}

__global__ void k_offsets() {
    int b = blockIdx.x;
    int i = b * 256 + threadIdx.x;
    if (i < N_NODES) {
        int boff = (b > 0) ? g_bscan[b - 1] : 0;
        int incl = g_scan[i] + boff;
        g_off[i + 1] = incl;
        g_cursor[i]  = incl - g_indeg[i];   // exclusive offset
        if (i == 0) g_off[0] = 0;
    }
}

__global__ void k_scatter(const int* __restrict__ esrc, const int* __restrict__ edst) {
    int e = blockIdx.x * blockDim.x + threadIdx.x;
    if (e < N_EDGES) {
        int d = edst[e];
        int p = atomicAdd(&g_cursor[d], 1);
        g_csr[p] = esrc[e];
    }
}

// ---------------- fp32 GEMM: Y[M,BN] = (A[M,K] * norm[:,None]) @ W[K,BN] -----
template <int BM, int BN, int BK, int TM, int TN>
__device__ __forceinline__ void gemm_core(const float* __restrict__ A,
                                          const float* __restrict__ W,
                                          const float* __restrict__ norm,
                                          float* __restrict__ Y,
                                          int M, int K) {
    constexpr int NT  = (BM / TM) * (BN / TN);
    constexpr int BKP = BK + 1;
    __shared__ float sA[BM * BKP];
    __shared__ float sB[BK * BN];

    const int tid = threadIdx.x;
    const int tx  = tid % (BN / TN);
    const int ty  = tid / (BN / TN);
    const int m0  = blockIdx.x * BM;

    float acc[TM][TN];
    #pragma unroll
    for (int i = 0; i < TM; i++)
        #pragma unroll
        for (int j = 0; j < TN; j++) acc[i][j] = 0.f;

    for (int k0 = 0; k0 < K; k0 += BK) {
        // load A tile (scaled by norm)
        #pragma unroll
        for (int i = tid; i < BM * BK / 4; i += NT) {
            int r = i / (BK / 4);
            int c = (i % (BK / 4)) * 4;
            int row = m0 + r;
            float4 v = make_float4(0.f, 0.f, 0.f, 0.f);
            if (row < M) {
                v = *(const float4*)&A[(size_t)row * K + k0 + c];
                float s = norm[row];
                v.x *= s; v.y *= s; v.z *= s; v.w *= s;
            }
            sA[r * BKP + c + 0] = v.x;
            sA[r * BKP + c + 1] = v.y;
            sA[r * BKP + c + 2] = v.z;
            sA[r * BKP + c + 3] = v.w;
        }
        // load W tile (full width BN)
        #pragma unroll
        for (int i = tid; i < BK * BN / 4; i += NT) {
            int r = i / (BN / 4);
            int c = (i % (BN / 4)) * 4;
            *(float4*)&sB[r * BN + c] = *(const float4*)&W[(size_t)(k0 + r) * BN + c];
        }
        __syncthreads();

        #pragma unroll
        for (int kk = 0; kk < BK; kk++) {
            float a[TM];
            #pragma unroll
            for (int i = 0; i < TM; i++) a[i] = sA[(ty * TM + i) * BKP + kk];
            float4 b = *(const float4*)&sB[kk * BN + tx * TN];
            #pragma unroll
            for (int i = 0; i < TM; i++) {
                acc[i][0] = fmaf(a[i], b.x, acc[i][0]);
                acc[i][1] = fmaf(a[i], b.y, acc[i][1]);
                acc[i][2] = fmaf(a[i], b.z, acc[i][2]);
                acc[i][3] = fmaf(a[i], b.w, acc[i][3]);
            }
        }
        __syncthreads();
    }

    #pragma unroll
    for (int i = 0; i < TM; i++) {
        int row = m0 + ty * TM + i;
        if (row < M) {
            float4 o = make_float4(acc[i][0], acc[i][1], acc[i][2], acc[i][3]);
            *(float4*)&Y[(size_t)row * BN + tx * TN] = o;
        }
    }
}

__global__ void __launch_bounds__(256) k_gemm1(const float* __restrict__ A,
                                               const float* __restrict__ W) {
    gemm_core<64, 128, 32, 8, 4>(A, W, g_outnorm, g_y1, N_NODES, F_IN);
}

__global__ void __launch_bounds__(128) k_gemm2(const float* __restrict__ W) {
    gemm_core<64, 64, 32, 8, 4>(g_h, W, g_outnorm, g_y2, N_NODES, F_HID);
}

// ---------------- aggregation (CSR gather, no atomics) -----------------------
// layer 1: one warp per node, 128 feats = 32 lanes x float4; relu epilogue
__global__ void __launch_bounds__(256) k_agg1(const float* __restrict__ b1) {
    int warp = (blockIdx.x * blockDim.x + threadIdx.x) >> 5;
    int lane = threadIdx.x & 31;
    if (warp >= N_NODES) return;
    int beg = g_off[warp], end = g_off[warp + 1];
    float4 acc = make_float4(0.f, 0.f, 0.f, 0.f);
    for (int j = beg; j < end; j++) {
        int s = g_csr[j];
        float4 v = *(const float4*)&g_y1[(size_t)s * F_HID + lane * 4];
        acc.x += v.x; acc.y += v.y; acc.z += v.z; acc.w += v.w;
    }
    float inn = g_innorm[warp];
    float4 bb = *(const float4*)&b1[lane * 4];
    float4 o;
    o.x = fmaxf(fmaf(acc.x, inn, bb.x), 0.f);
    o.y = fmaxf(fmaf(acc.y, inn, bb.y), 0.f);
    o.z = fmaxf(fmaf(acc.z, inn, bb.z), 0.f);
    o.w = fmaxf(fmaf(acc.w, inn, bb.w), 0.f);
    *(float4*)&g_h[(size_t)warp * F_HID + lane * 4] = o;
}

// layer 2: one warp per node, 64 feats = 32 lanes x float2; no relu
__global__ void __launch_bounds__(256) k_agg2(const float* __restrict__ b2,
                                              float* __restrict__ out) {
    int warp = (blockIdx.x * blockDim.x + threadIdx.x) >> 5;
    int lane = threadIdx.x & 31;
    if (warp >= N_NODES) return;
    int beg = g_off[warp], end = g_off[warp + 1];
    float2 acc = make_float2(0.f, 0.f);
    for (int j = beg; j < end; j++) {
        int s = g_csr[j];
        float2 v = *(const float2*)&g_y2[(size_t)s * F_OUT + lane * 2];
        acc.x += v.x; acc.y += v.y;
    }
    float inn = g_innorm[warp];
    float2 bb = *(const float2*)&b2[lane * 2];
    float2 o;
    o.x = fmaf(acc.x, inn, bb.x);
    o.y = fmaf(acc.y, inn, bb.y);
    *(float2*)&out[(size_t)warp * F_OUT + lane * 2] = o;
}

// ---------------- launch -----------------------------------------------------
extern "C" void kernel_launch(void* const* d_in, const int* in_sizes, int n_in,
                              void* d_out, int out_size) {
    const float* features = (const float*)d_in[0];
    const int*   esrc     = (const int*)  d_in[1];
    const int*   edst     = (const int*)  d_in[2];
    const float* W1       = (const float*)d_in[3];
    const float* b1       = (const float*)d_in[4];
    const float* W2       = (const float*)d_in[5];
    const float* b2       = (const float*)d_in[6];
    float* out = (float*)d_out;

    const int EB = (N_EDGES + 255) / 256;   // 3125
    const int MB = (N_NODES + 63) / 64;     // 782

    k_zero_deg <<<NBLK, 256>>>();
    k_degrees  <<<EB, 256>>>(esrc, edst);
    k_scan_block<<<NBLK, 256>>>();
    k_scan_bsum<<<1, 256>>>();
    k_offsets  <<<NBLK, 256>>>();
    k_scatter  <<<EB, 256>>>(esrc, edst);

    k_gemm1<<<MB, 256>>>(features, W1);
    k_agg1 <<<(N_NODES * 32 + 255) / 256, 256>>>(b1);
    k_gemm2<<<MB, 128>>>(W2);
    k_agg2 <<<(N_NODES * 32 + 255) / 256, 256>>>(b2, out);
}

// round 4
// speedup vs baseline: 1.3244x; 1.3244x over previous
#include <cuda_runtime.h>
#include <cuda_bf16.h>
#include <mma.h>
#include <cstdint>

using namespace nvcuda;

#define N_NODES 50000
#define PAD_NODES 50048      // 391 * 128, so GEMM epilogues can store unguarded
#define N_EDGES 800000
#define F_IN    512
#define F_HID   128
#define F_OUT   64
#define NBLK    196          // ceil(50000/256)

// ---------------- device scratch (static; no allocation allowed) -------------
__device__ int   g_indeg[N_NODES];
__device__ int   g_outdeg[N_NODES];
__device__ float g_outnorm[N_NODES];
__device__ float g_innorm[N_NODES];
__device__ int   g_scan[N_NODES];
__device__ int   g_bsum[256];
__device__ int   g_bscan[256];
__device__ int   g_off[N_NODES + 1];
__device__ int   g_cursor[N_NODES];
__device__ int   g_csr[N_EDGES];
__device__ float g_y1[(size_t)PAD_NODES * F_HID];
__device__ float g_h [(size_t)N_NODES  * F_HID];
__device__ float g_y2[(size_t)PAD_NODES * F_OUT];

__device__ __forceinline__ float tf32_rna_f(float f) {
    uint32_t r; asm("cvt.rna.tf32.f32 %0, %1;" : "=r"(r) : "f"(f));
    return __uint_as_float(r);
}

// ---------------- degree / CSR construction --------------------------------
__global__ void k_zero_deg() {
    int i = blockIdx.x * blockDim.x + threadIdx.x;
    if (i < N_NODES) { g_indeg[i] = 0; g_outdeg[i] = 0; }
}

__global__ void k_degrees(const int* __restrict__ esrc, const int* __restrict__ edst) {
    int e = blockIdx.x * blockDim.x + threadIdx.x;
    if (e < N_EDGES) {
        atomicAdd(&g_outdeg[esrc[e]], 1);
        atomicAdd(&g_indeg [edst[e]], 1);
    }
}

__global__ void k_scan_block() {
    __shared__ int sh[256];
    int t = threadIdx.x;
    int i = blockIdx.x * 256 + t;
    int v = (i < N_NODES) ? g_indeg[i] : 0;
    sh[t] = v;
    __syncthreads();
    #pragma unroll
    for (int o = 1; o < 256; o <<= 1) {
        int x = (t >= o) ? sh[t - o] : 0;
        __syncthreads();
        sh[t] += x;
        __syncthreads();
    }
    if (i < N_NODES) {
        g_scan[i] = sh[t];
        g_outnorm[i] = rsqrtf(fmaxf((float)g_outdeg[i], 1.0f));
        g_innorm [i] = rsqrtf(fmaxf((float)g_indeg [i], 1.0f));
    }
    if (t == 255) g_bsum[blockIdx.x] = sh[255];
}

__global__ void k_scan_bsum() {
    __shared__ int sh[256];
    int t = threadIdx.x;
    sh[t] = (t < NBLK) ? g_bsum[t] : 0;
    __syncthreads();
    #pragma unroll
    for (int o = 1; o < 256; o <<= 1) {
        int x = (t >= o) ? sh[t - o] : 0;
        __syncthreads();
        sh[t] += x;
        __syncthreads();
    }
    if (t < NBLK) g_bscan[t] = sh[t];
}

__global__ void k_offsets() {
    int b = blockIdx.x;
    int i = b * 256 + threadIdx.x;
    if (i < N_NODES) {
        int boff = (b > 0) ? g_bscan[b - 1] : 0;
        int incl = g_scan[i] + boff;
        g_off[i + 1] = incl;
        g_cursor[i]  = incl - g_indeg[i];
        if (i == 0) g_off[0] = 0;
    }
}

__global__ void k_scatter(const int* __restrict__ esrc, const int* __restrict__ edst) {
    int e = blockIdx.x * blockDim.x + threadIdx.x;
    if (e < N_EDGES) {
        int d = edst[e];
        int p = atomicAdd(&g_cursor[d], 1);
        g_csr[p] = esrc[e];
    }
}

// ---------------- WMMA tf32 GEMM: Y = (A * outnorm[:,None]) @ W -------------
// BM=128 rows/CTA, BN = full output width (128 or 64), BK=32.
// 256 threads, 8 warps, warp grid 4(M) x 2(N); warp tile 32 x BN/2.
// LAYER==1: A = features (param), Y = g_y1.  LAYER==2: A = g_h, Y = g_y2.
template <int BN, int KT, int LAYER>
__global__ void __launch_bounds__(256) k_wmma_gemm(const float* __restrict__ Ain,
                                                   const float* __restrict__ W) {
    constexpr int BM  = 128;
    constexpr int BK  = 32;
    constexpr int LDA = 40;        // 160B row stride (16B-aligned, conflict-light)
    constexpr int LDB = BN + 4;
    constexpr int WN  = BN / 2;    // warp tile N
    constexpr int FN  = WN / 16;   // wmma tiles per warp in N

    const float* A = (LAYER == 2) ? (const float*)g_h : Ain;
    float* Y = (LAYER == 1) ? g_y1 : g_y2;

    __shared__ float sA[BM * LDA];
    __shared__ float sB[BK * LDB];

    const int tid  = threadIdx.x;
    const int wid  = tid >> 5;
    const int wm   = wid >> 1;     // 0..3
    const int wn   = wid & 1;      // 0..1
    const int m0   = blockIdx.x * BM;

    wmma::fragment<wmma::accumulator, 16, 16, 8, float> c[2][FN];
    #pragma unroll
    for (int i = 0; i < 2; i++)
        #pragma unroll
        for (int j = 0; j < FN; j++) wmma::fill_fragment(c[i][j], 0.0f);

    // A-load mapping: thread -> (row = tid/2, col half = (tid&1)*16), 4 float4s
    const int arow  = tid >> 1;
    const int acol0 = (tid & 1) * 16;
    const int growA = m0 + arow;
    const bool okA  = growA < N_NODES;
    const float sc  = okA ? g_outnorm[growA] : 0.0f;
    const float* Arow = A + (size_t)growA * KT;

    for (int k0 = 0; k0 < KT; k0 += BK) {
        __syncthreads();
        // --- stage A (scaled + tf32-rounded) ---
        #pragma unroll
        for (int q = 0; q < 4; q++) {
            float4 v = okA ? *(const float4*)(Arow + k0 + acol0 + q * 4)
                           : make_float4(0.f, 0.f, 0.f, 0.f);
            float4 t;
            t.x = tf32_rna_f(v.x * sc);
            t.y = tf32_rna_f(v.y * sc);
            t.z = tf32_rna_f(v.z * sc);
            t.w = tf32_rna_f(v.w * sc);
            *(float4*)&sA[arow * LDA + acol0 + q * 4] = t;
        }
        // --- stage B (tf32-rounded), W is [KT x BN] row-major ---
        #pragma unroll
        for (int i = tid; i < BK * (BN / 4); i += 256) {
            int r = i / (BN / 4);
            int cc = (i % (BN / 4)) * 4;
            float4 v = *(const float4*)&W[(size_t)(k0 + r) * BN + cc];
            float4 t;
            t.x = tf32_rna_f(v.x);
            t.y = tf32_rna_f(v.y);
            t.z = tf32_rna_f(v.z);
            t.w = tf32_rna_f(v.w);
            *(float4*)&sB[r * LDB + cc] = t;
        }
        __syncthreads();

        // --- compute: 4 k-steps of 8 ---
        #pragma unroll
        for (int kk = 0; kk < BK; kk += 8) {
            wmma::fragment<wmma::matrix_a, 16, 16, 8, wmma::precision::tf32, wmma::row_major> a[2];
            wmma::fragment<wmma::matrix_b, 16, 16, 8, wmma::precision::tf32, wmma::row_major> b[FN];
            #pragma unroll
            for (int i = 0; i < 2; i++)
                wmma::load_matrix_sync(a[i], &sA[(wm * 32 + i * 16) * LDA + kk], LDA);
            #pragma unroll
            for (int j = 0; j < FN; j++)
                wmma::load_matrix_sync(b[j], &sB[kk * LDB + wn * WN + j * 16], LDB);
            #pragma unroll
            for (int i = 0; i < 2; i++)
                #pragma unroll
                for (int j = 0; j < FN; j++)
                    wmma::mma_sync(c[i][j], a[i], b[j], c[i][j]);
        }
    }

    // --- epilogue: unguarded stores into padded Y ---
    #pragma unroll
    for (int i = 0; i < 2; i++)
        #pragma unroll
        for (int j = 0; j < FN; j++) {
            float* dst = Y + (size_t)(m0 + wm * 32 + i * 16) * BN + wn * WN + j * 16;
            wmma::store_matrix_sync(dst, c[i][j], BN, wmma::mem_row_major);
        }
}

// ---------------- aggregation (CSR gather, no atomics) -----------------------
__global__ void __launch_bounds__(256) k_agg1(const float* __restrict__ b1) {
    int warp = (blockIdx.x * blockDim.x + threadIdx.x) >> 5;
    int lane = threadIdx.x & 31;
    if (warp >= N_NODES) return;
    int beg = g_off[warp], end = g_off[warp + 1];
    float4 acc = make_float4(0.f, 0.f, 0.f, 0.f);
    for (int j = beg; j < end; j++) {
        int s = g_csr[j];
        float4 v = *(const float4*)&g_y1[(size_t)s * F_HID + lane * 4];
        acc.x += v.x; acc.y += v.y; acc.z += v.z; acc.w += v.w;
    }
    float inn = g_innorm[warp];
    float4 bb = *(const float4*)&b1[lane * 4];
    float4 o;
    o.x = fmaxf(fmaf(acc.x, inn, bb.x), 0.f);
    o.y = fmaxf(fmaf(acc.y, inn, bb.y), 0.f);
    o.z = fmaxf(fmaf(acc.z, inn, bb.z), 0.f);
    o.w = fmaxf(fmaf(acc.w, inn, bb.w), 0.f);
    *(float4*)&g_h[(size_t)warp * F_HID + lane * 4] = o;
}

__global__ void __launch_bounds__(256) k_agg2(const float* __restrict__ b2,
                                              float* __restrict__ out) {
    int warp = (blockIdx.x * blockDim.x + threadIdx.x) >> 5;
    int lane = threadIdx.x & 31;
    if (warp >= N_NODES) return;
    int beg = g_off[warp], end = g_off[warp + 1];
    float2 acc = make_float2(0.f, 0.f);
    for (int j = beg; j < end; j++) {
        int s = g_csr[j];
        float2 v = *(const float2*)&g_y2[(size_t)s * F_OUT + lane * 2];
        acc.x += v.x; acc.y += v.y;
    }
    float inn = g_innorm[warp];
    float2 bb = *(const float2*)&b2[lane * 2];
    float2 o;
    o.x = fmaf(acc.x, inn, bb.x);
    o.y = fmaf(acc.y, inn, bb.y);
    *(float2*)&out[(size_t)warp * F_OUT + lane * 2] = o;
}

// ---------------- launch -----------------------------------------------------
extern "C" void kernel_launch(void* const* d_in, const int* in_sizes, int n_in,
                              void* d_out, int out_size) {
    const float* features = (const float*)d_in[0];
    const int*   esrc     = (const int*)  d_in[1];
    const int*   edst     = (const int*)  d_in[2];
    const float* W1       = (const float*)d_in[3];
    const float* b1       = (const float*)d_in[4];
    const float* W2       = (const float*)d_in[5];
    const float* b2       = (const float*)d_in[6];
    float* out = (float*)d_out;

    const int EB = (N_EDGES + 255) / 256;     // 3125
    const int GB = (N_NODES + 127) / 128;     // 391

    k_zero_deg  <<<NBLK, 256>>>();
    k_degrees   <<<EB, 256>>>(esrc, edst);
    k_scan_block<<<NBLK, 256>>>();
    k_scan_bsum <<<1, 256>>>();
    k_offsets   <<<NBLK, 256>>>();
    k_scatter   <<<EB, 256>>>(esrc, edst);

    k_wmma_gemm<128, 512, 1><<<GB, 256>>>(features, W1);
    k_agg1<<<(N_NODES * 32 + 255) / 256, 256>>>(b1);
    k_wmma_gemm<64, 128, 2><<<GB, 256>>>(nullptr, W2);
    k_agg2<<<(N_NODES * 32 + 255) / 256, 256>>>(b2, out);
}